// round 6
// baseline (speedup 1.0000x reference)
#include <cuda_runtime.h>
#include <math.h>

#define NIMG 256        // B*N = 64*4
#define NTHREADS 1024

typedef unsigned long long ull;

// ---- dynamic shared layout (bytes) ----
// SG/DG rows padded to 288 (dup of first 32) for wrap-free window reads
#define SM_CS   0                    // float2 [64][64]    = 32768
#define SM_SDB  (SM_CS + 32768)      // float4 [49][24]    = 18816
#define SM_WT   (SM_SDB + 18816)     // float2 [256]       = 2048
#define SM_WP   (SM_WT + 2048)       // ulonglong2 [256]   = 4096
#define SM_SG   (SM_WP + 4096)       // float2 [24][288]   = 55296
#define SM_DG   (SM_SG + 55296)      // float2 [24][288]   = 55296
#define SM_G0   (SM_DG + 55296)      // float2 [288]       = 2304
#define SM_CROP (SM_G0 + 2304)       // float  [4096]      = 16384
#define SM_RED  (SM_CROP + 16384)    // float  [32]        = 128
#define SM_TOTAL (SM_RED + 128)      // 187136 bytes

#define GSTRIDE 288

extern __shared__ char smem_raw[];

#define FMA2(d, a, b, c) \
    asm("fma.rn.f32x2 %0, %1, %2, %3;" : "=l"(d) : "l"(a), "l"(b), "l"(c))

__device__ __forceinline__ float2 u2f2(ull v) {
    float2 r;
    asm("mov.b64 {%0, %1}, %2;" : "=f"(r.x), "=f"(r.y) : "l"(v));
    return r;
}
__device__ __forceinline__ ull splat2(float f) {
    ull r;
    asm("mov.b64 %0, {%1, %1};" : "=l"(r) : "f"(f));
    return r;
}

__global__ void __launch_bounds__(NTHREADS, 1)
render_kernel(const float* __restrict__ X,  const float* __restrict__ Y,
              const float* __restrict__ Z,  const float* __restrict__ Aa,
              const float* __restrict__ Bg, const float* __restrict__ P,
              const float* __restrict__ phase0,
              float* __restrict__ out)
{
    float2*     Cs   = (float2*)    (smem_raw + SM_CS);
    float4*     SDB  = (float4*)    (smem_raw + SM_SDB);
    float2*     Wt   = (float2*)    (smem_raw + SM_WT);
    ulonglong2* Wp   = (ulonglong2*)(smem_raw + SM_WP);
    float2*     SG   = (float2*)    (smem_raw + SM_SG);
    float2*     DG   = (float2*)    (smem_raw + SM_DG);
    float2*     G0   = (float2*)    (smem_raw + SM_G0);
    float*      crop = (float*)     (smem_raw + SM_CROP);
    float*      red  = (float*)     (smem_raw + SM_RED);

    const int img  = blockIdx.x;
    const int tid  = threadIdx.x;
    const int lane = tid & 31;
    const int warp = tid >> 5;     // 0..31

    const float x = X[img], y = Y[img], z = Z[img];

    // ---- twiddle tables: W[k] = exp(2*pi*i*k/256) ----
    if (tid < 256) {
        float s, c;
        sincospif((float)tid * (1.0f / 128.0f), &s, &c);
        Wt[tid] = make_float2(c, s);
        Wp[tid] = make_ulonglong2(splat2(c), splat2(s));
    }

    // ---- Phase A: pupil C[a][b] (64x64, zero outside disk) ----
    const float k2pi = 6.283185307179586f / 256.0f;
    #pragma unroll
    for (int k = 0; k < 4; k++) {
        int idx = tid + k * NTHREADS;
        int a = idx >> 6, b = idx & 63;
        float us = (-1.0f + (float)a * (2.0f / 63.0f)) * (1.0f / 0.75f);
        float vs = (-1.0f + (float)b * (2.0f / 63.0f)) * (1.0f / 0.75f);
        float R = sqrtf(us * us + vs * vs);
        float2 c2 = make_float2(0.0f, 0.0f);
        if (R <= 1.0f) {
            float prop = sqrtf(fmaxf(1.0f - R * R, 0.0f));
            float psi = phase0[idx] + prop * z
                        - k2pi * ((float)(a - 32) * x + (float)(b - 32) * y);
            float sn, cs;
            sincosf(psi, &sn, &cs);
            c2 = make_float2(cs, sn);
        }
        Cs[idx] = c2;
    }
    __syncthreads();

    // ---- SDB: per-row b-fold sums. SDB[r][mb-1] = (S.r,S.i,D.i,D.r), a=r+8
    for (int idx = tid; idx < 49 * 24; idx += NTHREADS) {
        int r  = idx / 24;
        int mb = idx - r * 24 + 1;          // 1..24
        int a  = r + 8;
        float2 cu = Cs[a * 64 + 32 + mb];
        float2 cd = Cs[a * 64 + 32 - mb];
        SDB[idx] = make_float4(cu.x + cd.x, cu.y + cd.y,
                               cu.y - cd.y, cu.x - cd.x);
    }
    __syncthreads();

    // ---- Phase B (packed f32x2): row-paired, v-folded column DFT ----
    // dup-writes indices <32 into [256..287] pad for wrap-free window reads
    for (int i = 0; i < 4; i++) {
        int t = warp + 32 * i;
        if (t >= 100) break;
        int m  = t >> 2;
        int vb = t & 3;
        int v  = (vb << 5) + lane;          // 0..127

        float2 w0 = Wt[v];
        ull CC  = splat2(w0.x), SS  = splat2(w0.y);
        ull RC  = CC,           RS  = SS;
        ull NRS = splat2(-w0.y);
        const ull ZERO = 0;

        ull ACu = 0, ASu = 0, ACd = 0, ASd = 0;
        const ulonglong2* sup = (const ulonglong2*)(SDB + (24 + m) * 24);
        const ulonglong2* sdn = (const ulonglong2*)(SDB + (24 - m) * 24);

        if (m == 0) {
            #pragma unroll 6
            for (int mb = 0; mb < 24; mb++) {
                ulonglong2 sv = sup[mb];
                FMA2(ACu, CC, sv.x, ACu);
                FMA2(ASu, SS, sv.y, ASu);
                ull t1, t2;
                FMA2(t1, CC, RC, ZERO); FMA2(t2, CC, RS, ZERO);
                FMA2(CC, SS, NRS, t1);  FMA2(SS, SS, RC, t2);
            }
            float2 ac = u2f2(ACu), as = u2f2(ASu);
            float2 base = Cs[32 * 64 + 32];
            float2 glo = make_float2(base.x + ac.x - as.x, base.y + ac.y + as.y);
            float2 ghi = make_float2(base.x + ac.x + as.x, base.y + ac.y - as.y);
            G0[v] = glo;
            G0[(256 - v) & 255] = ghi;
            if (v < 32) G0[256 + v] = (v == 0) ? ghi : glo;
        } else {
            #pragma unroll 6
            for (int mb = 0; mb < 24; mb++) {
                ulonglong2 sv = sup[mb];
                ulonglong2 dv = sdn[mb];
                FMA2(ACu, CC, sv.x, ACu);
                FMA2(ASu, SS, sv.y, ASu);
                FMA2(ACd, CC, dv.x, ACd);
                FMA2(ASd, SS, dv.y, ASd);
                ull t1, t2;
                FMA2(t1, CC, RC, ZERO); FMA2(t2, CC, RS, ZERO);
                FMA2(CC, SS, NRS, t1);  FMA2(SS, SS, RC, t2);
            }
            float2 acu = u2f2(ACu), asu = u2f2(ASu);
            float2 acd = u2f2(ACd), asd = u2f2(ASd);
            float2 bu = Cs[(32 + m) * 64 + 32];
            float2 bd = Cs[(32 - m) * 64 + 32];
            float2 up_lo = make_float2(bu.x + acu.x - asu.x, bu.y + acu.y + asu.y);
            float2 up_hi = make_float2(bu.x + acu.x + asu.x, bu.y + acu.y - asu.y);
            float2 dn_lo = make_float2(bd.x + acd.x - asd.x, bd.y + acd.y + asd.y);
            float2 dn_hi = make_float2(bd.x + acd.x + asd.x, bd.y + acd.y - asd.y);
            int base = (m - 1) * GSTRIDE;
            int vh = (256 - v) & 255;
            float2 sg_lo = make_float2(up_lo.x + dn_lo.x, up_lo.y + dn_lo.y);
            float2 dg_lo = make_float2(up_lo.y - dn_lo.y, up_lo.x - dn_lo.x);
            float2 sg_hi = make_float2(up_hi.x + dn_hi.x, up_hi.y + dn_hi.y);
            float2 dg_hi = make_float2(up_hi.y - dn_hi.y, up_hi.x - dn_hi.x);
            SG[base + v]  = sg_lo;  DG[base + v]  = dg_lo;
            SG[base + vh] = sg_hi;  DG[base + vh] = dg_hi;
            if (v < 32) {
                SG[base + 256 + v] = (v == 0) ? sg_hi : sg_lo;
                DG[base + 256 + v] = (v == 0) ? dg_hi : dg_lo;
            }
        }
    }

    // ---- v = 128 column (sin = 0, cos = (-1)^mb) ----
    if (tid >= 896 && tid < 921) {
        int m = tid - 896;                  // 0..24
        float2 up = Cs[(32 + m) * 64 + 32];
        float2 dn = Cs[(32 - m) * 64 + 32];
        const float4* sup = SDB + (24 + m) * 24;
        const float4* sdn = SDB + (24 - m) * 24;
        float sgn = -1.f;
        #pragma unroll 6
        for (int mb = 0; mb < 24; mb++) {
            float4 su = sup[mb]; float4 sd = sdn[mb];
            up.x = fmaf(sgn, su.x, up.x); up.y = fmaf(sgn, su.y, up.y);
            dn.x = fmaf(sgn, sd.x, dn.x); dn.y = fmaf(sgn, sd.y, dn.y);
            sgn = -sgn;
        }
        if (m == 0) {
            G0[128] = up;
        } else {
            SG[(m - 1) * GSTRIDE + 128] = make_float2(up.x + dn.x, up.y + dn.y);
            DG[(m - 1) * GSTRIDE + 128] = make_float2(up.y - dn.y, up.x - dn.x);
        }
    }
    __syncthreads();

    // ---- Phase C: crop region (u-folded, 18 units) + 80x96 max-window (60) ----
    const int iu = (int)(((unsigned)__float2int_rn(x)) & 255u);
    const int iv = (int)(((unsigned)__float2int_rn(y)) & 255u);
    const int wu0 = (iu - 40) & 255;
    const int wv0 = (iv - 48) & 255;

    float lmax = 0.0f;
    const char* wp = (const char*)Wp;

    for (int i = 0; i < 3; i++) {
        int t = warp + 32 * i;
        if (t >= 78) break;

        if (t < 18) {
            // ---- crop unit: ut 0..8 -> u0 = 4*ut; vb 0..1 ----
            int ut = t >> 1;
            int vb = t & 1;
            int v  = vb ? (224 + lane) : lane;
            int u0 = ut << 2;

            int o0 = ((u0 + 0) << 4) & 4095, o1 = ((u0 + 1) << 4) & 4095;
            int o2 = ((u0 + 2) << 4) & 4095, o3 = ((u0 + 3) << 4) & 4095;
            ull c0 = 0, s0 = 0, c1 = 0, s1 = 0;
            ull c2 = 0, s2 = 0, c3 = 0, s3 = 0;

            const char* sgp = (const char*)(SG + v);
            const char* dgp = (const char*)(DG + v);
            #pragma unroll 4
            for (int m = 1; m <= 24; m++) {
                ull gs = *(const ull*)sgp;
                ull gd = *(const ull*)dgp;
                sgp += GSTRIDE * 8; dgp += GSTRIDE * 8;
                ulonglong2 w0 = *(const ulonglong2*)(wp + o0);
                ulonglong2 w1 = *(const ulonglong2*)(wp + o1);
                ulonglong2 w2 = *(const ulonglong2*)(wp + o2);
                ulonglong2 w3 = *(const ulonglong2*)(wp + o3);
                FMA2(c0, w0.x, gs, c0); FMA2(s0, w0.y, gd, s0);
                FMA2(c1, w1.x, gs, c1); FMA2(s1, w1.y, gd, s1);
                FMA2(c2, w2.x, gs, c2); FMA2(s2, w2.y, gd, s2);
                FMA2(c3, w3.x, gs, c3); FMA2(s3, w3.y, gd, s3);
                o0 = (o0 + ((u0 + 0) << 4)) & 4095;
                o1 = (o1 + ((u0 + 1) << 4)) & 4095;
                o2 = (o2 + ((u0 + 2) << 4)) & 4095;
                o3 = (o3 + ((u0 + 3) << 4)) & 4095;
            }

            float2 g0 = G0[v];
            int tcol = (v + 32) & 255;

            #pragma unroll
            for (int j = 0; j < 4; j++) {
                ull cj = (j == 0) ? c0 : (j == 1) ? c1 : (j == 2) ? c2 : c3;
                ull sj = (j == 0) ? s0 : (j == 1) ? s1 : (j == 2) ? s2 : s3;
                float2 ac = u2f2(cj);
                float2 as = u2f2(sj);
                float t1r = g0.x + ac.x, t1i = g0.y + ac.y;
                float orx = t1r - as.x, oix = t1i + as.y;   // out(u)
                float prx = t1r + as.x, pix = t1i - as.y;   // out(256-u)
                float p2a = fmaf(orx, orx, oix * oix);
                float p2b = fmaf(prx, prx, pix * pix);
                lmax = fmaxf(lmax, fmaxf(p2a, p2b));
                int u  = u0 + j;
                int sa = (u + 32) & 255;
                if (sa < 64) crop[(sa << 6) + tcol] = p2a;
                int sb = (32 - u) & 255;
                if (sb < 64) crop[(sb << 6) + tcol] = p2b;
            }
        } else {
            // ---- window unit: max-only, 80u x 96v around (iu, iv) ----
            int t2  = t - 18;                // 0..59
            int wvb = t2 / 20;               // 0..2
            int wt  = t2 - wvb * 20;         // 0..19
            int vbase = (wv0 + (wvb << 5)) & 255;
            int vidx  = vbase + lane;        // padded index <= 286
            int ub    = wu0 + (wt << 2);

            int u_0 = (ub    ) & 255, u_1 = (ub + 1) & 255;
            int u_2 = (ub + 2) & 255, u_3 = (ub + 3) & 255;
            int st0 = u_0 << 4, st1 = u_1 << 4, st2 = u_2 << 4, st3 = u_3 << 4;
            int o0 = st0, o1 = st1, o2 = st2, o3 = st3;
            ull c0 = 0, s0 = 0, c1 = 0, s1 = 0;
            ull c2 = 0, s2 = 0, c3 = 0, s3 = 0;

            const char* sgp = (const char*)(SG + vidx);
            const char* dgp = (const char*)(DG + vidx);
            #pragma unroll 4
            for (int m = 1; m <= 24; m++) {
                ull gs = *(const ull*)sgp;
                ull gd = *(const ull*)dgp;
                sgp += GSTRIDE * 8; dgp += GSTRIDE * 8;
                ulonglong2 w0 = *(const ulonglong2*)(wp + o0);
                ulonglong2 w1 = *(const ulonglong2*)(wp + o1);
                ulonglong2 w2 = *(const ulonglong2*)(wp + o2);
                ulonglong2 w3 = *(const ulonglong2*)(wp + o3);
                FMA2(c0, w0.x, gs, c0); FMA2(s0, w0.y, gd, s0);
                FMA2(c1, w1.x, gs, c1); FMA2(s1, w1.y, gd, s1);
                FMA2(c2, w2.x, gs, c2); FMA2(s2, w2.y, gd, s2);
                FMA2(c3, w3.x, gs, c3); FMA2(s3, w3.y, gd, s3);
                o0 = (o0 + st0) & 4095;
                o1 = (o1 + st1) & 4095;
                o2 = (o2 + st2) & 4095;
                o3 = (o3 + st3) & 4095;
            }

            float2 g0 = G0[vidx];
            #pragma unroll
            for (int j = 0; j < 4; j++) {
                ull cj = (j == 0) ? c0 : (j == 1) ? c1 : (j == 2) ? c2 : c3;
                ull sj = (j == 0) ? s0 : (j == 1) ? s1 : (j == 2) ? s2 : s3;
                float2 ac = u2f2(cj);
                float2 as = u2f2(sj);
                float orx = g0.x + ac.x - as.x;
                float oix = g0.y + ac.y + as.y;
                lmax = fmaxf(lmax, fmaf(orx, orx, oix * oix));
            }
        }
    }

    // ---- CTA max reduction ----
    #pragma unroll
    for (int o = 16; o > 0; o >>= 1)
        lmax = fmaxf(lmax, __shfl_xor_sync(0xFFFFFFFFu, lmax, o));
    if (lane == 0) red[warp] = lmax;
    __syncthreads();
    if (warp == 0) {
        float m = red[lane];
        #pragma unroll
        for (int o = 16; o > 0; o >>= 1)
            m = fmaxf(m, __shfl_xor_sync(0xFFFFFFFFu, m, o));
        if (lane == 0) red[0] = m;
    }
    __syncthreads();
    const float maxv = red[0];

    // ---- epilogue: atomic-accumulate (psf/max * A + bg) * mask into out[b] ----
    const float A    = Aa[img];
    const float bg   = Bg[img];
    const float mask = (P[img] > 0.5f) ? 1.0f : 0.0f;
    const float scale = (A / maxv) * mask;
    const float bgm   = bg * mask;
    float* outb = out + (size_t)(img >> 2) * 4096;
    #pragma unroll
    for (int k = 0; k < 4; k++) {
        int idx = tid + k * NTHREADS;
        atomicAdd(&outb[idx], fmaf(crop[idx], scale, bgm));
    }
}

extern "C" void kernel_launch(void* const* d_in, const int* in_sizes, int n_in,
                              void* d_out, int out_size)
{
    (void)in_sizes; (void)n_in;
    cudaMemsetAsync(d_out, 0, (size_t)out_size * sizeof(float));
    cudaFuncSetAttribute(render_kernel,
                         cudaFuncAttributeMaxDynamicSharedMemorySize, SM_TOTAL);
    render_kernel<<<NIMG, NTHREADS, SM_TOTAL>>>(
        (const float*)d_in[0], (const float*)d_in[1], (const float*)d_in[2],
        (const float*)d_in[3], (const float*)d_in[4], (const float*)d_in[5],
        (const float*)d_in[6], (float*)d_out);
}

// round 7
// speedup vs baseline: 1.0406x; 1.0406x over previous
#include <cuda_runtime.h>
#include <math.h>

#define NIMG 256        // B*N = 64*4
#define NTHREADS 1024

typedef unsigned long long ull;

// ---- dynamic shared layout (bytes) ----
#define SM_CSB  0                    // float2 [49] base col   = 512 (padded)
#define SM_SDB  (SM_CSB + 512)       // float4 [49][24]        = 18816
#define SM_WT   (SM_SDB + 18816)     // float2 [256]           = 2048
#define SM_WP   (SM_WT + 2048)       // ulonglong2 [256]       = 4096
#define SM_SGDG (SM_WP + 4096)       // float4 [24][288]       = 110592
#define SM_G0   (SM_SGDG + 110592)   // float2 [288]           = 2304
#define SM_CROP (SM_G0 + 2304)       // float  [4096]          = 16384
#define SM_RED  (SM_CROP + 16384)    // float  [32]            = 128
#define SM_TOTAL (SM_RED + 128)      // 154880 bytes

#define GSTRIDE 288

extern __shared__ char smem_raw[];

#define FMA2(d, a, b, c) \
    asm("fma.rn.f32x2 %0, %1, %2, %3;" : "=l"(d) : "l"(a), "l"(b), "l"(c))

__device__ __forceinline__ float2 u2f2(ull v) {
    float2 r;
    asm("mov.b64 {%0, %1}, %2;" : "=f"(r.x), "=f"(r.y) : "l"(v));
    return r;
}
__device__ __forceinline__ ull splat2(float f) {
    ull r;
    asm("mov.b64 %0, {%1, %1};" : "=l"(r) : "f"(f));
    return r;
}

__device__ __forceinline__ float2 pupil_pt(int a, int b, float x, float y,
                                           float z, const float* __restrict__ ph)
{
    float us = (float)(2 * a - 63) * (1.0f / 47.25f);
    float vs = (float)(2 * b - 63) * (1.0f / 47.25f);
    float R  = sqrtf(us * us + vs * vs);
    if (R > 1.0f) return make_float2(0.0f, 0.0f);
    float prop = sqrtf(fmaxf(1.0f - R * R, 0.0f));
    float psi = ph[a * 64 + b] + prop * z
              - (6.283185307179586f / 256.0f)
                * ((float)(a - 32) * x + (float)(b - 32) * y);
    float sn, cs;
    sincosf(psi, &sn, &cs);
    return make_float2(cs, sn);
}

__global__ void __launch_bounds__(NTHREADS, 1)
render_kernel(const float* __restrict__ X,  const float* __restrict__ Y,
              const float* __restrict__ Z,  const float* __restrict__ Aa,
              const float* __restrict__ Bg, const float* __restrict__ P,
              const float* __restrict__ phase0,
              float* __restrict__ out)
{
    float2*     CsB  = (float2*)    (smem_raw + SM_CSB);
    float4*     SDB  = (float4*)    (smem_raw + SM_SDB);
    float2*     Wt   = (float2*)    (smem_raw + SM_WT);
    ulonglong2* Wp   = (ulonglong2*)(smem_raw + SM_WP);
    float4*     SGDG = (float4*)    (smem_raw + SM_SGDG);
    float2*     G0   = (float2*)    (smem_raw + SM_G0);
    float*      crop = (float*)     (smem_raw + SM_CROP);
    float*      red  = (float*)     (smem_raw + SM_RED);

    const int img  = blockIdx.x;
    const int tid  = threadIdx.x;
    const int lane = tid & 31;
    const int warp = tid >> 5;     // 0..31

    const float x = X[img], y = Y[img], z = Z[img];

    // ---- twiddle tables: W[k] = exp(2*pi*i*k/256) ----
    if (tid < 256) {
        float s, c;
        sincospif((float)tid * (1.0f / 128.0f), &s, &c);
        Wt[tid] = make_float2(c, s);
        Wp[tid] = make_ulonglong2(splat2(c), splat2(s));
    }

    // ---- fused Phase A + SDB: thread per (row r, fold q) pair ----
    // SDB[r][q-1] = (S.r, S.i, D.i, D.r) with S/D = C[a][32+q] +/- C[a][32-q]
    for (int idx = tid; idx < 49 * 25; idx += NTHREADS) {
        int r = idx / 25;
        int q = idx - r * 25;               // 0..24
        int a = r + 8;
        if (q == 0) {
            CsB[r] = pupil_pt(a, 32, x, y, z, phase0);
        } else {
            float2 cu = pupil_pt(a, 32 + q, x, y, z, phase0);
            float2 cd = pupil_pt(a, 32 - q, x, y, z, phase0);
            SDB[r * 24 + (q - 1)] = make_float4(cu.x + cd.x, cu.y + cd.y,
                                                cu.y - cd.y, cu.x - cd.x);
        }
    }
    __syncthreads();

    // ---- Phase B (packed f32x2): row-paired, v-folded column DFT ----
    // elliptical trip bound: columns beyond pupil disk are exactly zero
    for (int i = 0; i < 4; i++) {
        int t = warp + 32 * i;
        if (t >= 100) break;
        int m  = t >> 2;
        int vb = t & 3;
        int v  = (vb << 5) + lane;          // 0..127

        int mm = 2 * m - 1;
        float wrad = 2232.5625f - (float)(mm * mm);
        int qe = min(24, (int)((sqrtf(wrad) - 1.0f) * 0.5f) + 2);

        float2 w0 = Wt[v];
        ull CC  = splat2(w0.x), SS  = splat2(w0.y);
        ull RC  = CC,           RS  = SS;
        ull NRS = splat2(-w0.y);
        const ull ZERO = 0;

        ull ACu = 0, ASu = 0, ACd = 0, ASd = 0;
        const ulonglong2* sup = (const ulonglong2*)(SDB + (24 + m) * 24);
        const ulonglong2* sdn = (const ulonglong2*)(SDB + (24 - m) * 24);

        if (m == 0) {
            #pragma unroll 4
            for (int mb = 0; mb < qe; mb++) {
                ulonglong2 sv = sup[mb];
                FMA2(ACu, CC, sv.x, ACu);
                FMA2(ASu, SS, sv.y, ASu);
                ull t1, t2;
                FMA2(t1, CC, RC, ZERO); FMA2(t2, CC, RS, ZERO);
                FMA2(CC, SS, NRS, t1);  FMA2(SS, SS, RC, t2);
            }
            float2 ac = u2f2(ACu), as = u2f2(ASu);
            float2 base = CsB[24];
            float2 glo = make_float2(base.x + ac.x - as.x, base.y + ac.y + as.y);
            float2 ghi = make_float2(base.x + ac.x + as.x, base.y + ac.y - as.y);
            G0[v] = glo;
            G0[(256 - v) & 255] = ghi;
            if (v < 32) G0[256 + v] = (v == 0) ? ghi : glo;
        } else {
            #pragma unroll 4
            for (int mb = 0; mb < qe; mb++) {
                ulonglong2 sv = sup[mb];
                ulonglong2 dv = sdn[mb];
                FMA2(ACu, CC, sv.x, ACu);
                FMA2(ASu, SS, sv.y, ASu);
                FMA2(ACd, CC, dv.x, ACd);
                FMA2(ASd, SS, dv.y, ASd);
                ull t1, t2;
                FMA2(t1, CC, RC, ZERO); FMA2(t2, CC, RS, ZERO);
                FMA2(CC, SS, NRS, t1);  FMA2(SS, SS, RC, t2);
            }
            float2 acu = u2f2(ACu), asu = u2f2(ASu);
            float2 acd = u2f2(ACd), asd = u2f2(ASd);
            float2 bu = CsB[24 + m];
            float2 bd = CsB[24 - m];
            float2 up_lo = make_float2(bu.x + acu.x - asu.x, bu.y + acu.y + asu.y);
            float2 up_hi = make_float2(bu.x + acu.x + asu.x, bu.y + acu.y - asu.y);
            float2 dn_lo = make_float2(bd.x + acd.x - asd.x, bd.y + acd.y + asd.y);
            float2 dn_hi = make_float2(bd.x + acd.x + asd.x, bd.y + acd.y - asd.y);
            int base = (m - 1) * GSTRIDE;
            int vh = (256 - v) & 255;
            float4 lo4 = make_float4(up_lo.x + dn_lo.x, up_lo.y + dn_lo.y,
                                     up_lo.y - dn_lo.y, up_lo.x - dn_lo.x);
            float4 hi4 = make_float4(up_hi.x + dn_hi.x, up_hi.y + dn_hi.y,
                                     up_hi.y - dn_hi.y, up_hi.x - dn_hi.x);
            SGDG[base + v]  = lo4;
            SGDG[base + vh] = hi4;
            if (v < 32) SGDG[base + 256 + v] = (v == 0) ? hi4 : lo4;
        }
    }

    // ---- v = 128 column (sin = 0, cos = (-1)^q) ----
    if (tid >= 896 && tid < 921) {
        int m = tid - 896;                  // 0..24
        int mm = 2 * m - 1;
        float wrad = 2232.5625f - (float)(mm * mm);
        int qe = min(24, (int)((sqrtf(wrad) - 1.0f) * 0.5f) + 2);
        float2 up = CsB[24 + m];
        float2 dn = CsB[24 - m];
        const float4* sup = SDB + (24 + m) * 24;
        const float4* sdn = SDB + (24 - m) * 24;
        float sgn = -1.f;
        #pragma unroll 4
        for (int mb = 0; mb < qe; mb++) {
            float4 su = sup[mb]; float4 sd = sdn[mb];
            up.x = fmaf(sgn, su.x, up.x); up.y = fmaf(sgn, su.y, up.y);
            dn.x = fmaf(sgn, sd.x, dn.x); dn.y = fmaf(sgn, sd.y, dn.y);
            sgn = -sgn;
        }
        if (m == 0) {
            G0[128] = up;
        } else {
            SGDG[(m - 1) * GSTRIDE + 128] =
                make_float4(up.x + dn.x, up.y + dn.y,
                            up.y - dn.y, up.x - dn.x);
        }
    }
    __syncthreads();

    // ---- Phase C: crop (u-folded, 18 units, tile 4)
    //              + 80u x 96v max-window (30 units, tile 8) ----
    const int iu = (int)(((unsigned)__float2int_rn(x)) & 255u);
    const int iv = (int)(((unsigned)__float2int_rn(y)) & 255u);
    const int wu0 = (iu - 40) & 255;
    const int wv0 = (iv - 48) & 255;

    float lmax = 0.0f;
    const char* wp = (const char*)Wp;

    for (int i = 0; i < 2; i++) {
        int t = warp + 32 * i;
        if (t >= 48) break;

        if (t < 18) {
            // ---- crop unit: ut 0..8 -> u0 = 4*ut; vb 0..1 ----
            int ut = t >> 1;
            int vb = t & 1;
            int v  = vb ? (224 + lane) : lane;
            int u0 = ut << 2;

            int o0 = ((u0 + 0) << 4) & 4095, o1 = ((u0 + 1) << 4) & 4095;
            int o2 = ((u0 + 2) << 4) & 4095, o3 = ((u0 + 3) << 4) & 4095;
            ull c0 = 0, s0 = 0, c1 = 0, s1 = 0;
            ull c2 = 0, s2 = 0, c3 = 0, s3 = 0;

            const char* gp = (const char*)(SGDG + v);
            #pragma unroll 4
            for (int m = 1; m <= 24; m++) {
                ulonglong2 gsd = *(const ulonglong2*)gp;
                gp += GSTRIDE * 16;
                ulonglong2 w0 = *(const ulonglong2*)(wp + o0);
                ulonglong2 w1 = *(const ulonglong2*)(wp + o1);
                ulonglong2 w2 = *(const ulonglong2*)(wp + o2);
                ulonglong2 w3 = *(const ulonglong2*)(wp + o3);
                FMA2(c0, w0.x, gsd.x, c0); FMA2(s0, w0.y, gsd.y, s0);
                FMA2(c1, w1.x, gsd.x, c1); FMA2(s1, w1.y, gsd.y, s1);
                FMA2(c2, w2.x, gsd.x, c2); FMA2(s2, w2.y, gsd.y, s2);
                FMA2(c3, w3.x, gsd.x, c3); FMA2(s3, w3.y, gsd.y, s3);
                o0 = (o0 + ((u0 + 0) << 4)) & 4095;
                o1 = (o1 + ((u0 + 1) << 4)) & 4095;
                o2 = (o2 + ((u0 + 2) << 4)) & 4095;
                o3 = (o3 + ((u0 + 3) << 4)) & 4095;
            }

            float2 g0 = G0[v];
            int tcol = (v + 32) & 255;

            #pragma unroll
            for (int j = 0; j < 4; j++) {
                ull cj = (j == 0) ? c0 : (j == 1) ? c1 : (j == 2) ? c2 : c3;
                ull sj = (j == 0) ? s0 : (j == 1) ? s1 : (j == 2) ? s2 : s3;
                float2 ac = u2f2(cj);
                float2 as = u2f2(sj);
                float t1r = g0.x + ac.x, t1i = g0.y + ac.y;
                float orx = t1r - as.x, oix = t1i + as.y;   // out(u)
                float prx = t1r + as.x, pix = t1i - as.y;   // out(256-u)
                float p2a = fmaf(orx, orx, oix * oix);
                float p2b = fmaf(prx, prx, pix * pix);
                lmax = fmaxf(lmax, fmaxf(p2a, p2b));
                int u  = u0 + j;
                int sa = (u + 32) & 255;
                if (sa < 64) crop[(sa << 6) + tcol] = p2a;
                int sb = (32 - u) & 255;
                if (sb < 64) crop[(sb << 6) + tcol] = p2b;
            }
        } else {
            // ---- window unit (tile 8): max-only, 80u x 96v at (iu, iv) ----
            int t2  = t - 18;                // 0..29
            int wvb = t2 / 10;               // 0..2
            int wt  = t2 - wvb * 10;         // 0..9
            int vbase = (wv0 + (wvb << 5)) & 255;
            int vidx  = vbase + lane;        // padded index <= 286
            int ub    = wu0 + (wt << 3);

            int st0 = (((ub + 0) & 255) << 4), st1 = (((ub + 1) & 255) << 4);
            int st2 = (((ub + 2) & 255) << 4), st3 = (((ub + 3) & 255) << 4);
            int st4 = (((ub + 4) & 255) << 4), st5 = (((ub + 5) & 255) << 4);
            int st6 = (((ub + 6) & 255) << 4), st7 = (((ub + 7) & 255) << 4);
            int o0 = st0, o1 = st1, o2 = st2, o3 = st3;
            int o4 = st4, o5 = st5, o6 = st6, o7 = st7;
            ull c0 = 0, s0 = 0, c1 = 0, s1 = 0;
            ull c2 = 0, s2 = 0, c3 = 0, s3 = 0;
            ull c4 = 0, s4 = 0, c5 = 0, s5 = 0;
            ull c6 = 0, s6 = 0, c7 = 0, s7 = 0;

            const char* gp = (const char*)(SGDG + vidx);
            #pragma unroll 4
            for (int m = 1; m <= 24; m++) {
                ulonglong2 gsd = *(const ulonglong2*)gp;
                gp += GSTRIDE * 16;
                ulonglong2 w0 = *(const ulonglong2*)(wp + o0);
                ulonglong2 w1 = *(const ulonglong2*)(wp + o1);
                ulonglong2 w2 = *(const ulonglong2*)(wp + o2);
                ulonglong2 w3 = *(const ulonglong2*)(wp + o3);
                FMA2(c0, w0.x, gsd.x, c0); FMA2(s0, w0.y, gsd.y, s0);
                FMA2(c1, w1.x, gsd.x, c1); FMA2(s1, w1.y, gsd.y, s1);
                FMA2(c2, w2.x, gsd.x, c2); FMA2(s2, w2.y, gsd.y, s2);
                FMA2(c3, w3.x, gsd.x, c3); FMA2(s3, w3.y, gsd.y, s3);
                o0 = (o0 + st0) & 4095;
                o1 = (o1 + st1) & 4095;
                o2 = (o2 + st2) & 4095;
                o3 = (o3 + st3) & 4095;
                ulonglong2 w4 = *(const ulonglong2*)(wp + o4);
                ulonglong2 w5 = *(const ulonglong2*)(wp + o5);
                ulonglong2 w6 = *(const ulonglong2*)(wp + o6);
                ulonglong2 w7 = *(const ulonglong2*)(wp + o7);
                FMA2(c4, w4.x, gsd.x, c4); FMA2(s4, w4.y, gsd.y, s4);
                FMA2(c5, w5.x, gsd.x, c5); FMA2(s5, w5.y, gsd.y, s5);
                FMA2(c6, w6.x, gsd.x, c6); FMA2(s6, w6.y, gsd.y, s6);
                FMA2(c7, w7.x, gsd.x, c7); FMA2(s7, w7.y, gsd.y, s7);
                o4 = (o4 + st4) & 4095;
                o5 = (o5 + st5) & 4095;
                o6 = (o6 + st6) & 4095;
                o7 = (o7 + st7) & 4095;
            }

            float2 g0 = G0[vidx];
            float gr = g0.x, gi = g0.y;
            #pragma unroll
            for (int j = 0; j < 8; j++) {
                ull cj, sj;
                switch (j) {
                    case 0: cj = c0; sj = s0; break;
                    case 1: cj = c1; sj = s1; break;
                    case 2: cj = c2; sj = s2; break;
                    case 3: cj = c3; sj = s3; break;
                    case 4: cj = c4; sj = s4; break;
                    case 5: cj = c5; sj = s5; break;
                    case 6: cj = c6; sj = s6; break;
                    default: cj = c7; sj = s7; break;
                }
                float2 ac = u2f2(cj);
                float2 as = u2f2(sj);
                float orx = gr + ac.x - as.x;
                float oix = gi + ac.y + as.y;
                lmax = fmaxf(lmax, fmaf(orx, orx, oix * oix));
            }
        }
    }

    // ---- CTA max reduction ----
    #pragma unroll
    for (int o = 16; o > 0; o >>= 1)
        lmax = fmaxf(lmax, __shfl_xor_sync(0xFFFFFFFFu, lmax, o));
    if (lane == 0) red[warp] = lmax;
    __syncthreads();
    if (warp == 0) {
        float m = red[lane];
        #pragma unroll
        for (int o = 16; o > 0; o >>= 1)
            m = fmaxf(m, __shfl_xor_sync(0xFFFFFFFFu, m, o));
        if (lane == 0) red[0] = m;
    }
    __syncthreads();
    const float maxv = red[0];

    // ---- epilogue: atomic-accumulate (psf/max * A + bg) * mask into out[b] ----
    const float A    = Aa[img];
    const float bg   = Bg[img];
    const float mask = (P[img] > 0.5f) ? 1.0f : 0.0f;
    const float scale = (A / maxv) * mask;
    const float bgm   = bg * mask;
    float* outb = out + (size_t)(img >> 2) * 4096;
    #pragma unroll
    for (int k = 0; k < 4; k++) {
        int idx = tid + k * NTHREADS;
        atomicAdd(&outb[idx], fmaf(crop[idx], scale, bgm));
    }
}

extern "C" void kernel_launch(void* const* d_in, const int* in_sizes, int n_in,
                              void* d_out, int out_size)
{
    (void)in_sizes; (void)n_in;
    cudaMemsetAsync(d_out, 0, (size_t)out_size * sizeof(float));
    cudaFuncSetAttribute(render_kernel,
                         cudaFuncAttributeMaxDynamicSharedMemorySize, SM_TOTAL);
    render_kernel<<<NIMG, NTHREADS, SM_TOTAL>>>(
        (const float*)d_in[0], (const float*)d_in[1], (const float*)d_in[2],
        (const float*)d_in[3], (const float*)d_in[4], (const float*)d_in[5],
        (const float*)d_in[6], (float*)d_out);
}